// round 13
// baseline (speedup 1.0000x reference)
#include <cuda_runtime.h>
#include <cstdint>
#include <math.h>

#define B_ 64
#define S_ 512
#define H_ 1024
#define E_ 768
#define C_ (H_ + E_)

#define MTILE 128     // s rows per CTA
#define NTILE 256     // c cols per CTA
#define NCT 7         // 4 text c-tiles + 3 aspect c-tiles
#define KC 32         // K chunk (bf16 elems); row = 32 hi + 32 lo bf16 = 128B (SW128)

// smem layout (dynamic)
#define OFF_TMEM 0
#define OFF_BAR0 8
#define OFF_BAR1 16
#define OFF_WC   64          // 256 floats
#define OFF_RED  2048        // 256 floats
#define OFF_BUF  4096
// stage: A rows (128) then B rows (256), each row 128B = hi[32 bf16]|lo[32 bf16]
#define A_OFF 0
#define B_OFF 16384
#define STAGE 49152
#define SMEM_TOTAL (OFF_BUF + 2 * STAGE)   // 102400 -> 2 CTAs/SM

// partial scores per (b, ctile, s)
__device__ float g_part[B_ * NCT * S_];

// idesc: c=F32(1)@4, a=BF16(1)@7, b=BF16(1)@10, N/8@17, M/16@24
#define IDESC ((1u<<4) | (1u<<7) | (1u<<10) | ((NTILE/8)<<17) | ((MTILE/16)<<24))

// SW128 K-major smem descriptor base: layout=2, version=1, SBO=64, LBO=1
#define DESC_BASE ((2ull<<61) | (1ull<<46) | (64ull<<32) | (1ull<<16))

// ---------------- arch-portable helpers ----------------
__device__ __forceinline__ uint32_t smem_u32(const void* p) {
    uint32_t a;
    asm("{ .reg .u64 t; cvta.to.shared.u64 t, %1; cvt.u32.u64 %0, t; }"
        : "=r"(a) : "l"(p));
    return a;
}
__device__ __forceinline__ uint32_t pack_bf16(float a, float b) { // a->low16, b->high16
    uint32_t r;
    asm("cvt.rn.bf16x2.f32 %0, %1, %2;" : "=r"(r) : "f"(b), "f"(a));
    return r;
}
// bf16 split: hi = rn(x) as bf16; lo = rn(x - hi) as bf16. 2 elements per call.
__device__ __forceinline__ void split2(float x0, float x1, uint32_t &h, uint32_t &l) {
    h = pack_bf16(x0, x1);
    const float h0 = __uint_as_float(h << 16);
    const float h1 = __uint_as_float(h & 0xFFFF0000u);
    l = pack_bf16(x0 - h0, x1 - h1);
}
__device__ __forceinline__ int sw128(int off) { return off ^ ((off >> 3) & 0x70); }

// ---------------- sm_103a-only helpers (tcgen05 ISA) ----------------
#if defined(__CUDA_ARCH_FEAT_SM103_ALL)
__device__ __forceinline__ uint32_t elect_one() {
    uint32_t p;
    asm volatile("{ .reg .pred p; elect.sync _|p, 0xFFFFFFFF; selp.b32 %0, 1, 0, p; }"
                 : "=r"(p));
    return p;
}
__device__ __forceinline__ void bar_init(uint32_t addr, uint32_t cnt) {
    asm volatile("mbarrier.init.shared.b64 [%0], %1;" :: "r"(addr), "r"(cnt) : "memory");
}
__device__ __forceinline__ void bar_wait(uint32_t addr, uint32_t parity) {
    asm volatile(
        "{\n\t.reg .pred P;\n\t"
        "WL%=:\n\t"
        "mbarrier.try_wait.parity.acquire.cta.shared::cta.b64 P, [%0], %1, 0x989680;\n\t"
        "@P bra WD%=;\n\t"
        "bra WL%=;\n\t"
        "WD%=:\n\t}"
        :: "r"(addr), "r"(parity) : "memory");
}
__device__ __forceinline__ void mma_bf16(uint32_t d, uint64_t a, uint64_t b,
                                         uint32_t idesc, uint32_t en) {
    asm volatile(
        "{\n\t.reg .pred p;\n\tsetp.ne.u32 p, %4, 0;\n\t"
        "tcgen05.mma.cta_group::1.kind::f16 [%0], %1, %2, %3, p;\n\t}"
        :: "r"(d), "l"(a), "l"(b), "r"(idesc), "r"(en) : "memory");
}
__device__ __forceinline__ void mma_commit(uint32_t bar) {
    asm volatile(
        "tcgen05.commit.cta_group::1.mbarrier::arrive::one.shared::cluster.b64 [%0];"
        :: "r"(bar) : "memory");
}
__device__ __forceinline__ void ldtm32(uint32_t* r, uint32_t ta) {
    asm volatile(
        "tcgen05.ld.sync.aligned.32x32b.x32.b32 "
        "{%0,%1,%2,%3,%4,%5,%6,%7,%8,%9,%10,%11,%12,%13,%14,%15,"
        "%16,%17,%18,%19,%20,%21,%22,%23,%24,%25,%26,%27,%28,%29,%30,%31}, [%32];"
        : "=r"(r[0]),"=r"(r[1]),"=r"(r[2]),"=r"(r[3]),"=r"(r[4]),"=r"(r[5]),"=r"(r[6]),"=r"(r[7]),
          "=r"(r[8]),"=r"(r[9]),"=r"(r[10]),"=r"(r[11]),"=r"(r[12]),"=r"(r[13]),"=r"(r[14]),"=r"(r[15]),
          "=r"(r[16]),"=r"(r[17]),"=r"(r[18]),"=r"(r[19]),"=r"(r[20]),"=r"(r[21]),"=r"(r[22]),"=r"(r[23]),
          "=r"(r[24]),"=r"(r[25]),"=r"(r[26]),"=r"(r[27]),"=r"(r[28]),"=r"(r[29]),"=r"(r[30]),"=r"(r[31])
        : "r"(ta));
}
#endif  // __CUDA_ARCH_FEAT_SM103_ALL

// Groups of 8 consecutive fp32 per thread-slot: A = 512 groups (2/thread),
// B = 1024 groups (4/thread). rg holds 12 float4 (2 per group).
__device__ __forceinline__ void load_chunk(const float* __restrict__ gA,
                                           const float* __restrict__ gB,
                                           int K, int k0, int tid, float4* rg)
{
    #pragma unroll
    for (int i = 0; i < 2; i++) {
        const int gi = tid + i * 256;
        const int row = gi >> 2, g = gi & 3;
        const float* p = gA + (size_t)row * K + k0 + g * 8;
        rg[2 * i]     = __ldg((const float4*)p);
        rg[2 * i + 1] = __ldg((const float4*)(p + 4));
    }
    #pragma unroll
    for (int i = 0; i < 4; i++) {
        const int gi = tid + i * 256;
        const int row = gi >> 2, g = gi & 3;
        const float* p = gB + (size_t)row * K + k0 + g * 8;
        rg[4 + 2 * i] = __ldg((const float4*)p);
        rg[5 + 2 * i] = __ldg((const float4*)(p + 4));
    }
}

__device__ __forceinline__ void store_chunk(char* base, int tid, const float4* rg)
{
    #pragma unroll
    for (int i = 0; i < 6; i++) {
        const int isB = (i >= 2);
        const int gi = isB ? (tid + (i - 2) * 256) : (tid + i * 256);
        const int row = gi >> 2, g = gi & 3;
        char* dst = base + (isB ? B_OFF : A_OFF);
        const int off = row * 128 + g * 16;          // hi bytes [0,64) of the row
        const float4 v0 = rg[2 * i], v1 = rg[2 * i + 1];
        uint4 h, l;
        split2(v0.x, v0.y, h.x, l.x);
        split2(v0.z, v0.w, h.y, l.y);
        split2(v1.x, v1.y, h.z, l.z);
        split2(v1.z, v1.w, h.w, l.w);
        *(uint4*)(dst + sw128(off))      = h;
        *(uint4*)(dst + sw128(off + 64)) = l;        // lo bytes [64,128)
    }
}

// ---------------------------------------------------------------------------
// Kernel 1: tcgen05 bf16 3-pass GEMM + tanh + w_combine partial reduction.
// CTA = (stile, ctile, b). D[s=128, c=256] in TMEM.
// ---------------------------------------------------------------------------
__global__ __launch_bounds__(256, 2)
void score_kernel(const float* __restrict__ text,
                  const float* __restrict__ aspect,
                  const float* __restrict__ w_text,
                  const float* __restrict__ w_aspect,
                  const float* __restrict__ w_combine)
{
    extern __shared__ char sm[];
    const int tid = threadIdx.x;
    const int s0 = blockIdx.x * MTILE;
    const int ct = blockIdx.y;
    const int b  = blockIdx.z;

    // operand pointers for this c-tile
    int K, cg0;
    const float* gA;
    const float* gB;
    if (ct < 4) {
        K = H_; cg0 = ct * 256;
        gA = text   + ((size_t)b * S_ + s0) * H_;
        gB = w_text + (size_t)b * H_ * H_ + (size_t)cg0 * H_;
    } else {
        K = E_; const int c0 = (ct - 4) * 256; cg0 = H_ + c0;
        gA = aspect   + ((size_t)b * S_ + s0) * E_;
        gB = w_aspect + (size_t)b * E_ * E_ + (size_t)c0 * E_;
    }

#if defined(__CUDA_ARCH_FEAT_SM103_ALL)
    // ======================= tcgen05 path (sm_103a) ========================
    const uint32_t smb = smem_u32(sm);
    const int wid  = tid >> 5;
    const int lane = tid & 31;

    if (wid == 0) {
        asm volatile("tcgen05.alloc.cta_group::1.sync.aligned.shared::cta.b32 [%0], %1;"
                     :: "r"(smb + OFF_TMEM), "r"(256) : "memory");
        asm volatile("tcgen05.relinquish_alloc_permit.cta_group::1.sync.aligned;");
    }
    if (tid == 0) { bar_init(smb + OFF_BAR0, 1); bar_init(smb + OFF_BAR1, 1); }
    __syncthreads();
    uint32_t tmem;
    asm("ld.shared.b32 %0, [%1];" : "=r"(tmem) : "r"(smb + OFF_TMEM));

    const int nchunks = K / KC;   // 32 (text) or 24 (aspect)

    // w_combine tile into smem
    ((float*)(sm + OFF_WC))[tid] = w_combine[(size_t)b * C_ + cg0 + tid];

    // -------- K-chunk pipeline --------
    float4 rg[12];
    load_chunk(gA, gB, K, 0, tid, rg);

    int u0 = 0, u1 = 0, w0 = 0, w1 = 0;
    for (int c = 0; c < nchunks; c++) {
        const int buf = c & 1;
        // wait until the MMA that last read this buffer has completed
        if (buf == 0) { if (u0 > w0) { bar_wait(smb + OFF_BAR0, (u0 - 1) & 1); w0 = u0; } }
        else          { if (u1 > w1) { bar_wait(smb + OFF_BAR1, (u1 - 1) & 1); w1 = u1; } }

        store_chunk(sm + OFF_BUF + buf * STAGE, tid, rg);
        // issue next chunk's LDGs now; latency hides behind sync + MMA
        if (c + 1 < nchunks)
            load_chunk(gA, gB, K, (c + 1) * KC, tid, rg);

        asm volatile("fence.proxy.async.shared::cta;" ::: "memory");
        __syncthreads();

        if (wid == 0) {
            if (elect_one()) {
                const uint32_t sb = smb + OFF_BUF + buf * STAGE;
                const uint64_t dA = DESC_BASE | (((sb + A_OFF) >> 4) & 0x3FFF);
                const uint64_t dB = DESC_BASE | (((sb + B_OFF) >> 4) & 0x3FFF);
                // K=16 bf16 per MMA = 32B = desc +2. hi slices +0,+2 ; lo +4,+6
                #pragma unroll
                for (int ks = 0; ks < 2; ks++)
                    mma_bf16(tmem, dA + 2 * ks,     dB + 2 * ks, IDESC,
                             (c != 0) || (ks != 0));              // hiA*hiB
                #pragma unroll
                for (int ks = 0; ks < 2; ks++)
                    mma_bf16(tmem, dA + 4 + 2 * ks, dB + 2 * ks, IDESC, 1u);  // loA*hiB
                #pragma unroll
                for (int ks = 0; ks < 2; ks++)
                    mma_bf16(tmem, dA + 2 * ks, dB + 4 + 2 * ks, IDESC, 1u);  // hiA*loB
                mma_commit(smb + (buf ? OFF_BAR1 : OFF_BAR0));
            }
        }
        if (buf == 0) u0++; else u1++;
    }

    // drain: last commit tracks all prior MMAs (in-order pipe)
    {
        const int lb = (nchunks - 1) & 1;
        if (lb == 0) { if (u0 > w0) { bar_wait(smb + OFF_BAR0, (u0 - 1) & 1); w0 = u0; } }
        else         { if (u1 > w1) { bar_wait(smb + OFF_BAR1, (u1 - 1) & 1); w1 = u1; } }
    }
    asm volatile("tcgen05.fence::after_thread_sync;" ::: "memory");

    // -------- epilogue: tanh + dot with w_combine, per-thread over c --------
    const float* wcs = (const float*)(sm + OFF_WC);
    const int colbase = (wid >= 4) ? 128 : 0;
    float acc = 0.f;
    #pragma unroll
    for (int cb = 0; cb < 128; cb += 32) {
        uint32_t r[32];
        ldtm32(r, tmem + colbase + cb);
        asm volatile("tcgen05.wait::ld.sync.aligned;" ::: "memory");
        #pragma unroll
        for (int j = 0; j < 32; j++)
            acc += tanhf(__uint_as_float(r[j])) * wcs[colbase + cb + j];
    }
    asm volatile("tcgen05.fence::before_thread_sync;" ::: "memory");

    float* red = (float*)(sm + OFF_RED);
    red[wid * 32 + lane] = acc;
    __syncthreads();
    if (wid < 4) {
        const float v = red[wid * 32 + lane] + red[(wid + 4) * 32 + lane];
        g_part[((size_t)b * NCT + ct) * S_ + s0 + wid * 32 + lane] = v;
    }
    __syncthreads();
    if (wid == 0) {
        asm volatile("tcgen05.dealloc.cta_group::1.sync.aligned.b32 %0, %1;"
                     :: "r"(tmem), "r"(256));
    }
#else
    // ================== portable fallback (compute_103 PTX pass) ==========
    float* wcs = (float*)(sm + OFF_WC);
    wcs[tid] = w_combine[(size_t)b * C_ + cg0 + tid];
    __syncthreads();

    const int sl   = tid >> 1;          // 0..127
    const int half = tid & 1;           // c half
    float acc = 0.f;
    for (int cc = 0; cc < 128; cc++) {
        const int c = half * 128 + cc;
        const float* ar = gA + (size_t)sl * K;
        const float* br = gB + (size_t)c * K;
        float d = 0.f;
        for (int k = 0; k < K; k++) d += ar[k] * br[k];
        acc += tanhf(d) * wcs[c];
    }
    float* red = (float*)(sm + OFF_RED);
    red[tid] = acc;
    __syncthreads();
    if (half == 0)
        g_part[((size_t)b * NCT + ct) * S_ + s0 + sl] = red[tid] + red[tid + 1];
#endif
}

// ---------------------------------------------------------------------------
// Kernel 2: reduce c-tile partials + softmax over S. weight -> d_out[0:B*S).
// ---------------------------------------------------------------------------
__global__ void softmax_kernel(float* __restrict__ out_w)
{
    __shared__ float sh[S_];
    const int b = blockIdx.x;
    const int t = threadIdx.x;

    float x = 0.f;
    #pragma unroll
    for (int ctl = 0; ctl < NCT; ctl++)
        x += g_part[((size_t)b * NCT + ctl) * S_ + t];

    sh[t] = x;
    __syncthreads();
    for (int st = 256; st > 0; st >>= 1) {
        if (t < st) sh[t] = fmaxf(sh[t], sh[t + st]);
        __syncthreads();
    }
    const float mx = sh[0];
    __syncthreads();

    const float e = expf(x - mx);
    sh[t] = e;
    __syncthreads();
    for (int st = 256; st > 0; st >>= 1) {
        if (t < st) sh[t] += sh[t + st];
        __syncthreads();
    }
    out_w[(size_t)b * S_ + t] = e / sh[0];
}

// ---------------------------------------------------------------------------
// Kernel 3: out[b,h] = sum_s text[b,s,h] * weight[b,s].
// ---------------------------------------------------------------------------
__global__ __launch_bounds__(256)
void out_kernel(const float* __restrict__ text,
                const float* __restrict__ weight,
                float* __restrict__ outp)
{
    __shared__ float w[S_];
    const int b = blockIdx.y;
    const int h = blockIdx.x * 256 + threadIdx.x;

    for (int i = threadIdx.x; i < S_; i += 256)
        w[i] = weight[(size_t)b * S_ + i];
    __syncthreads();

    const float* tb = text + (size_t)b * S_ * H_ + h;
    float a0 = 0.f, a1 = 0.f, a2 = 0.f, a3 = 0.f;
    #pragma unroll 4
    for (int s = 0; s < S_; s += 4) {
        a0 += tb[(size_t)(s + 0) * H_] * w[s + 0];
        a1 += tb[(size_t)(s + 1) * H_] * w[s + 1];
        a2 += tb[(size_t)(s + 2) * H_] * w[s + 2];
        a3 += tb[(size_t)(s + 3) * H_] * w[s + 3];
    }
    outp[(size_t)b * H_ + h] = (a0 + a1) + (a2 + a3);
}

// ---------------------------------------------------------------------------
extern "C" void kernel_launch(void* const* d_in, const int* in_sizes, int n_in,
                              void* d_out, int out_size)
{
    const float* text      = (const float*)d_in[0];
    const float* aspect    = (const float*)d_in[1];
    const float* w_text    = (const float*)d_in[2];
    const float* w_aspect  = (const float*)d_in[3];
    const float* w_combine = (const float*)d_in[4];
    float* out = (float*)d_out;

    static bool attr_set = false;
    if (!attr_set) {
        cudaFuncSetAttribute(score_kernel,
                             cudaFuncAttributeMaxDynamicSharedMemorySize, SMEM_TOTAL);
        attr_set = true;
    }

    dim3 grid(S_ / MTILE, NCT, B_);
    score_kernel<<<grid, 256, SMEM_TOTAL>>>(text, aspect, w_text, w_aspect, w_combine);
    softmax_kernel<<<B_, S_>>>(out);
    out_kernel<<<dim3(H_ / 256, B_), 256>>>(text, out, out + (size_t)B_ * S_);
}

// round 14
// speedup vs baseline: 1.0023x; 1.0023x over previous
#include <cuda_runtime.h>
#include <cstdint>
#include <math.h>

#define B_ 64
#define S_ 512
#define H_ 1024
#define E_ 768
#define C_ (H_ + E_)

#define MTILE 128     // s rows per CTA
#define NTILE 256     // c cols per CTA
#define NCT 7         // 4 text c-tiles + 3 aspect c-tiles
#define KC 32         // K chunk (bf16 elems); row = 32 hi + 32 lo bf16 = 128B (SW128)

// smem layout (dynamic)
#define OFF_TMEM 0
#define OFF_BAR0 8
#define OFF_BAR1 16
#define OFF_WC   64          // 256 floats
#define OFF_RED  2048        // 256 floats
#define OFF_BUF  4096
// stage: A rows (128) then B rows (256), each row 128B = hi[32 bf16]|lo[32 bf16]
#define A_OFF 0
#define B_OFF 16384
#define STAGE 49152
#define SMEM_TOTAL (OFF_BUF + 2 * STAGE)   // 102400 -> 2 CTAs/SM

// partial scores per (b, ctile, s)
__device__ float g_part[B_ * NCT * S_];

// idesc: c=F32(1)@4, a=BF16(1)@7, b=BF16(1)@10, N/8@17, M/16@24
#define IDESC ((1u<<4) | (1u<<7) | (1u<<10) | ((NTILE/8)<<17) | ((MTILE/16)<<24))

// SW128 K-major smem descriptor base: layout=2, version=1, SBO=64, LBO=1
#define DESC_BASE ((2ull<<61) | (1ull<<46) | (64ull<<32) | (1ull<<16))

// ---------------- arch-portable helpers ----------------
__device__ __forceinline__ uint32_t smem_u32(const void* p) {
    uint32_t a;
    asm("{ .reg .u64 t; cvta.to.shared.u64 t, %1; cvt.u32.u64 %0, t; }"
        : "=r"(a) : "l"(p));
    return a;
}
__device__ __forceinline__ uint32_t pack_bf16(float a, float b) { // a->low16, b->high16
    uint32_t r;
    asm("cvt.rn.bf16x2.f32 %0, %1, %2;" : "=r"(r) : "f"(b), "f"(a));
    return r;
}
// bf16 split: hi = rn(x) as bf16; lo = rn(x - hi) as bf16. 2 elements per call.
__device__ __forceinline__ void split2(float x0, float x1, uint32_t &h, uint32_t &l) {
    h = pack_bf16(x0, x1);
    const float h0 = __uint_as_float(h << 16);
    const float h1 = __uint_as_float(h & 0xFFFF0000u);
    l = pack_bf16(x0 - h0, x1 - h1);
}
__device__ __forceinline__ int sw128(int off) { return off ^ ((off >> 3) & 0x70); }

// ---------------- sm_103a-only helpers (tcgen05 ISA) ----------------
#if defined(__CUDA_ARCH_FEAT_SM103_ALL)
__device__ __forceinline__ uint32_t elect_one() {
    uint32_t p;
    asm volatile("{ .reg .pred p; elect.sync _|p, 0xFFFFFFFF; selp.b32 %0, 1, 0, p; }"
                 : "=r"(p));
    return p;
}
__device__ __forceinline__ void bar_init(uint32_t addr, uint32_t cnt) {
    asm volatile("mbarrier.init.shared.b64 [%0], %1;" :: "r"(addr), "r"(cnt) : "memory");
}
__device__ __forceinline__ void bar_wait(uint32_t addr, uint32_t parity) {
    asm volatile(
        "{\n\t.reg .pred P;\n\t"
        "WL%=:\n\t"
        "mbarrier.try_wait.parity.acquire.cta.shared::cta.b64 P, [%0], %1, 0x989680;\n\t"
        "@P bra WD%=;\n\t"
        "bra WL%=;\n\t"
        "WD%=:\n\t}"
        :: "r"(addr), "r"(parity) : "memory");
}
__device__ __forceinline__ void mma_bf16(uint32_t d, uint64_t a, uint64_t b,
                                         uint32_t idesc, uint32_t en) {
    asm volatile(
        "{\n\t.reg .pred p;\n\tsetp.ne.u32 p, %4, 0;\n\t"
        "tcgen05.mma.cta_group::1.kind::f16 [%0], %1, %2, %3, p;\n\t}"
        :: "r"(d), "l"(a), "l"(b), "r"(idesc), "r"(en) : "memory");
}
__device__ __forceinline__ void mma_commit(uint32_t bar) {
    asm volatile(
        "tcgen05.commit.cta_group::1.mbarrier::arrive::one.shared::cluster.b64 [%0];"
        :: "r"(bar) : "memory");
}
__device__ __forceinline__ void ldtm32(uint32_t* r, uint32_t ta) {
    asm volatile(
        "tcgen05.ld.sync.aligned.32x32b.x32.b32 "
        "{%0,%1,%2,%3,%4,%5,%6,%7,%8,%9,%10,%11,%12,%13,%14,%15,"
        "%16,%17,%18,%19,%20,%21,%22,%23,%24,%25,%26,%27,%28,%29,%30,%31}, [%32];"
        : "=r"(r[0]),"=r"(r[1]),"=r"(r[2]),"=r"(r[3]),"=r"(r[4]),"=r"(r[5]),"=r"(r[6]),"=r"(r[7]),
          "=r"(r[8]),"=r"(r[9]),"=r"(r[10]),"=r"(r[11]),"=r"(r[12]),"=r"(r[13]),"=r"(r[14]),"=r"(r[15]),
          "=r"(r[16]),"=r"(r[17]),"=r"(r[18]),"=r"(r[19]),"=r"(r[20]),"=r"(r[21]),"=r"(r[22]),"=r"(r[23]),
          "=r"(r[24]),"=r"(r[25]),"=r"(r[26]),"=r"(r[27]),"=r"(r[28]),"=r"(r[29]),"=r"(r[30]),"=r"(r[31])
        : "r"(ta));
}
#endif  // __CUDA_ARCH_FEAT_SM103_ALL

// Groups of 8 consecutive fp32 per thread-slot: A = 512 groups (2/thread),
// B = 1024 groups (4/thread). rg holds 12 float4 (2 per group).
__device__ __forceinline__ void load_chunk(const float* __restrict__ gA,
                                           const float* __restrict__ gB,
                                           int K, int k0, int tid, float4* rg)
{
    #pragma unroll
    for (int i = 0; i < 2; i++) {
        const int gi = tid + i * 256;
        const int row = gi >> 2, g = gi & 3;
        const float* p = gA + (size_t)row * K + k0 + g * 8;
        rg[2 * i]     = __ldg((const float4*)p);
        rg[2 * i + 1] = __ldg((const float4*)(p + 4));
    }
    #pragma unroll
    for (int i = 0; i < 4; i++) {
        const int gi = tid + i * 256;
        const int row = gi >> 2, g = gi & 3;
        const float* p = gB + (size_t)row * K + k0 + g * 8;
        rg[4 + 2 * i] = __ldg((const float4*)p);
        rg[5 + 2 * i] = __ldg((const float4*)(p + 4));
    }
}

__device__ __forceinline__ void store_chunk(char* base, int tid, const float4* rg)
{
    #pragma unroll
    for (int i = 0; i < 6; i++) {
        const int isB = (i >= 2);
        const int gi = isB ? (tid + (i - 2) * 256) : (tid + i * 256);
        const int row = gi >> 2, g = gi & 3;
        char* dst = base + (isB ? B_OFF : A_OFF);
        const int off = row * 128 + g * 16;          // hi bytes [0,64) of the row
        const float4 v0 = rg[2 * i], v1 = rg[2 * i + 1];
        uint4 h, l;
        split2(v0.x, v0.y, h.x, l.x);
        split2(v0.z, v0.w, h.y, l.y);
        split2(v1.x, v1.y, h.z, l.z);
        split2(v1.z, v1.w, h.w, l.w);
        *(uint4*)(dst + sw128(off))      = h;
        *(uint4*)(dst + sw128(off + 64)) = l;        // lo bytes [64,128)
    }
}

// ---------------------------------------------------------------------------
// Kernel 1: tcgen05 bf16 3-pass GEMM + tanh + w_combine partial reduction.
// CTA = (stile, ctile, b). D[s=128, c=256] in TMEM.
// ---------------------------------------------------------------------------
__global__ __launch_bounds__(256, 2)
void score_kernel(const float* __restrict__ text,
                  const float* __restrict__ aspect,
                  const float* __restrict__ w_text,
                  const float* __restrict__ w_aspect,
                  const float* __restrict__ w_combine)
{
    extern __shared__ char sm[];
    const int tid = threadIdx.x;
    const int s0 = blockIdx.x * MTILE;
    const int ct = blockIdx.y;
    const int b  = blockIdx.z;

    // operand pointers for this c-tile
    int K, cg0;
    const float* gA;
    const float* gB;
    if (ct < 4) {
        K = H_; cg0 = ct * 256;
        gA = text   + ((size_t)b * S_ + s0) * H_;
        gB = w_text + (size_t)b * H_ * H_ + (size_t)cg0 * H_;
    } else {
        K = E_; const int c0 = (ct - 4) * 256; cg0 = H_ + c0;
        gA = aspect   + ((size_t)b * S_ + s0) * E_;
        gB = w_aspect + (size_t)b * E_ * E_ + (size_t)c0 * E_;
    }

#if defined(__CUDA_ARCH_FEAT_SM103_ALL)
    // ======================= tcgen05 path (sm_103a) ========================
    const uint32_t smb = smem_u32(sm);
    const int wid  = tid >> 5;
    const int lane = tid & 31;

    if (wid == 0) {
        asm volatile("tcgen05.alloc.cta_group::1.sync.aligned.shared::cta.b32 [%0], %1;"
                     :: "r"(smb + OFF_TMEM), "r"(256) : "memory");
        asm volatile("tcgen05.relinquish_alloc_permit.cta_group::1.sync.aligned;");
    }
    if (tid == 0) { bar_init(smb + OFF_BAR0, 1); bar_init(smb + OFF_BAR1, 1); }
    __syncthreads();
    uint32_t tmem;
    asm("ld.shared.b32 %0, [%1];" : "=r"(tmem) : "r"(smb + OFF_TMEM));

    const int nchunks = K / KC;   // 32 (text) or 24 (aspect)

    // w_combine tile into smem
    ((float*)(sm + OFF_WC))[tid] = w_combine[(size_t)b * C_ + cg0 + tid];

    // -------- K-chunk pipeline --------
    float4 rg[12];
    load_chunk(gA, gB, K, 0, tid, rg);

    int u0 = 0, u1 = 0, w0 = 0, w1 = 0;
    for (int c = 0; c < nchunks; c++) {
        const int buf = c & 1;
        // wait until the MMA that last read this buffer has completed
        if (buf == 0) { if (u0 > w0) { bar_wait(smb + OFF_BAR0, (u0 - 1) & 1); w0 = u0; } }
        else          { if (u1 > w1) { bar_wait(smb + OFF_BAR1, (u1 - 1) & 1); w1 = u1; } }

        store_chunk(sm + OFF_BUF + buf * STAGE, tid, rg);
        // issue next chunk's LDGs now; latency hides behind sync + MMA
        if (c + 1 < nchunks)
            load_chunk(gA, gB, K, (c + 1) * KC, tid, rg);

        asm volatile("fence.proxy.async.shared::cta;" ::: "memory");
        __syncthreads();

        if (wid == 0) {
            if (elect_one()) {
                const uint32_t sb = smb + OFF_BUF + buf * STAGE;
                const uint64_t dA = DESC_BASE | (((sb + A_OFF) >> 4) & 0x3FFF);
                const uint64_t dB = DESC_BASE | (((sb + B_OFF) >> 4) & 0x3FFF);
                // K=16 bf16 per MMA = 32B = desc +2. hi slices +0,+2 ; lo +4,+6
                #pragma unroll
                for (int ks = 0; ks < 2; ks++)
                    mma_bf16(tmem, dA + 2 * ks,     dB + 2 * ks, IDESC,
                             (c != 0) || (ks != 0));              // hiA*hiB
                #pragma unroll
                for (int ks = 0; ks < 2; ks++)
                    mma_bf16(tmem, dA + 4 + 2 * ks, dB + 2 * ks, IDESC, 1u);  // loA*hiB
                #pragma unroll
                for (int ks = 0; ks < 2; ks++)
                    mma_bf16(tmem, dA + 2 * ks, dB + 4 + 2 * ks, IDESC, 1u);  // hiA*loB
                mma_commit(smb + (buf ? OFF_BAR1 : OFF_BAR0));
            }
        }
        if (buf == 0) u0++; else u1++;
    }

    // drain: last commit tracks all prior MMAs (in-order pipe)
    {
        const int lb = (nchunks - 1) & 1;
        if (lb == 0) { if (u0 > w0) { bar_wait(smb + OFF_BAR0, (u0 - 1) & 1); w0 = u0; } }
        else         { if (u1 > w1) { bar_wait(smb + OFF_BAR1, (u1 - 1) & 1); w1 = u1; } }
    }
    asm volatile("tcgen05.fence::after_thread_sync;" ::: "memory");

    // -------- epilogue: tanh + dot with w_combine, per-thread over c --------
    const float* wcs = (const float*)(sm + OFF_WC);
    const int colbase = (wid >= 4) ? 128 : 0;
    float acc = 0.f;
    #pragma unroll
    for (int cb = 0; cb < 128; cb += 32) {
        uint32_t r[32];
        ldtm32(r, tmem + colbase + cb);
        asm volatile("tcgen05.wait::ld.sync.aligned;" ::: "memory");
        #pragma unroll
        for (int j = 0; j < 32; j++)
            acc += tanhf(__uint_as_float(r[j])) * wcs[colbase + cb + j];
    }
    asm volatile("tcgen05.fence::before_thread_sync;" ::: "memory");

    float* red = (float*)(sm + OFF_RED);
    red[wid * 32 + lane] = acc;
    __syncthreads();
    if (wid < 4) {
        const float v = red[wid * 32 + lane] + red[(wid + 4) * 32 + lane];
        g_part[((size_t)b * NCT + ct) * S_ + s0 + wid * 32 + lane] = v;
    }
    __syncthreads();
    if (wid == 0) {
        asm volatile("tcgen05.dealloc.cta_group::1.sync.aligned.b32 %0, %1;"
                     :: "r"(tmem), "r"(256));
    }
#else
    // ================== portable fallback (compute_103 PTX pass) ==========
    float* wcs = (float*)(sm + OFF_WC);
    wcs[tid] = w_combine[(size_t)b * C_ + cg0 + tid];
    __syncthreads();

    const int sl   = tid >> 1;          // 0..127
    const int half = tid & 1;           // c half
    float acc = 0.f;
    for (int cc = 0; cc < 128; cc++) {
        const int c = half * 128 + cc;
        const float* ar = gA + (size_t)sl * K;
        const float* br = gB + (size_t)c * K;
        float d = 0.f;
        for (int k = 0; k < K; k++) d += ar[k] * br[k];
        acc += tanhf(d) * wcs[c];
    }
    float* red = (float*)(sm + OFF_RED);
    red[tid] = acc;
    __syncthreads();
    if (half == 0)
        g_part[((size_t)b * NCT + ct) * S_ + s0 + sl] = red[tid] + red[tid + 1];
#endif
}

// ---------------------------------------------------------------------------
// Kernel 2: reduce c-tile partials + softmax over S. weight -> d_out[0:B*S).
// ---------------------------------------------------------------------------
__global__ void softmax_kernel(float* __restrict__ out_w)
{
    __shared__ float sh[S_];
    const int b = blockIdx.x;
    const int t = threadIdx.x;

    float x = 0.f;
    #pragma unroll
    for (int ctl = 0; ctl < NCT; ctl++)
        x += g_part[((size_t)b * NCT + ctl) * S_ + t];

    sh[t] = x;
    __syncthreads();
    for (int st = 256; st > 0; st >>= 1) {
        if (t < st) sh[t] = fmaxf(sh[t], sh[t + st]);
        __syncthreads();
    }
    const float mx = sh[0];
    __syncthreads();

    const float e = expf(x - mx);
    sh[t] = e;
    __syncthreads();
    for (int st = 256; st > 0; st >>= 1) {
        if (t < st) sh[t] += sh[t + st];
        __syncthreads();
    }
    out_w[(size_t)b * S_ + t] = e / sh[0];
}

// ---------------------------------------------------------------------------
// Kernel 3: out[b,h] = sum_s text[b,s,h] * weight[b,s].
// ---------------------------------------------------------------------------
__global__ __launch_bounds__(256)
void out_kernel(const float* __restrict__ text,
                const float* __restrict__ weight,
                float* __restrict__ outp)
{
    __shared__ float w[S_];
    const int b = blockIdx.y;
    const int h = blockIdx.x * 256 + threadIdx.x;

    for (int i = threadIdx.x; i < S_; i += 256)
        w[i] = weight[(size_t)b * S_ + i];
    __syncthreads();

    const float* tb = text + (size_t)b * S_ * H_ + h;
    float a0 = 0.f, a1 = 0.f, a2 = 0.f, a3 = 0.f;
    #pragma unroll 4
    for (int s = 0; s < S_; s += 4) {
        a0 += tb[(size_t)(s + 0) * H_] * w[s + 0];
        a1 += tb[(size_t)(s + 1) * H_] * w[s + 1];
        a2 += tb[(size_t)(s + 2) * H_] * w[s + 2];
        a3 += tb[(size_t)(s + 3) * H_] * w[s + 3];
    }
    outp[(size_t)b * H_ + h] = (a0 + a1) + (a2 + a3);
}

// ---------------------------------------------------------------------------
extern "C" void kernel_launch(void* const* d_in, const int* in_sizes, int n_in,
                              void* d_out, int out_size)
{
    const float* text      = (const float*)d_in[0];
    const float* aspect    = (const float*)d_in[1];
    const float* w_text    = (const float*)d_in[2];
    const float* w_aspect  = (const float*)d_in[3];
    const float* w_combine = (const float*)d_in[4];
    float* out = (float*)d_out;

    static bool attr_set = false;
    if (!attr_set) {
        cudaFuncSetAttribute(score_kernel,
                             cudaFuncAttributeMaxDynamicSharedMemorySize, SMEM_TOTAL);
        attr_set = true;
    }

    dim3 grid(S_ / MTILE, NCT, B_);
    score_kernel<<<grid, 256, SMEM_TOTAL>>>(text, aspect, w_text, w_aspect, w_combine);
    softmax_kernel<<<B_, S_>>>(out);
    out_kernel<<<dim3(H_ / 256, B_), 256>>>(text, out, out + (size_t)B_ * S_);
}